// round 5
// baseline (speedup 1.0000x reference)
#include <cuda_runtime.h>
#include <cuda_bf16.h>
#include <cstdint>

#define EPS 1e-5f

// ---------------- scratch (static __device__ — no allocation) ----------------
// conv weights in bf16-split u2 layout: [b][chunk(CINPAD/16)][tap(25)][kpair(8)][COUT]
__device__ uint2 g_k1[16 * 1 * 25 * 8 * 16];
__device__ uint2 g_k2[16 * 1 * 25 * 8 * 16];
__device__ uint2 g_k3[16 * 1 * 25 * 8 * 32];
__device__ uint2 g_k4[16 * 2 * 25 * 8 * 32];
__device__ uint2 g_k5[16 * 2 * 25 * 8 * 64];
__device__ uint2 g_k6[16 * 4 * 25 * 8 * 64];
__device__ float g_k7[16 * 4 * 64];

__device__ float g_t1[16 * 16 * 256 * 256];
__device__ float g_t2[16 * 16 * 256 * 256];
__device__ float g_t3[16 * 16 * 128 * 128];
__device__ float g_t4[16 * 32 * 128 * 128];
__device__ float g_t5[16 * 32 * 128 * 128];
__device__ float g_t6[16 * 64 * 128 * 128];
__device__ float g_t7[16 * 64 * 128 * 128];
__device__ float g_t8[16 * 4 * 128 * 128];

// per-layer BN affine: [layer][b*C + c][2] ; max C = 64
__device__ float g_aff[7 * 16 * 64 * 2];

// ---------------- helpers ----------------
__device__ __forceinline__ uint2 bsplit2(float v0, float v1) {
    __nv_bfloat16 h0 = __float2bfloat16(v0);
    __nv_bfloat16 h1 = __float2bfloat16(v1);
    float l0 = v0 - __bfloat162float(h0);
    float l1 = v1 - __bfloat162float(h1);
    __nv_bfloat162 hi, lo;
    hi.x = h0;
    hi.y = h1;
    lo.x = __float2bfloat16(l0);
    lo.y = __float2bfloat16(l1);
    uint2 u;
    u.x = *reinterpret_cast<uint32_t*>(&hi);
    u.y = *reinterpret_cast<uint32_t*>(&lo);
    return u;
}

__device__ __forceinline__ void mma_bf16(float c[4], uint32_t a0, uint32_t a1, uint32_t a2,
                                         uint32_t a3, uint32_t b0, uint32_t b1) {
    asm volatile(
        "mma.sync.aligned.m16n8k16.row.col.f32.bf16.bf16.f32 "
        "{%0,%1,%2,%3},{%4,%5,%6,%7},{%8,%9},{%0,%1,%2,%3};"
        : "+f"(c[0]), "+f"(c[1]), "+f"(c[2]), "+f"(c[3])
        : "r"(a0), "r"(a1), "r"(a2), "r"(a3), "r"(b0), "r"(b1));
}

// ---------------- per-batch weight generation ----------------
// plain fp32 layout (for 1x1 conv)
__global__ void genw_kernel(const float* __restrict__ w, const float* __restrict__ bias,
                            const int* __restrict__ action, float* __restrict__ out, int od) {
    int i = blockIdx.x * blockDim.x + threadIdx.x;
    int total = od * 16;
    if (i >= total) return;
    int b = i / od, o = i - b * od;
    out[i] = w[o * 6 + action[b]] + bias[o];
}

// bf16-split u2 layout for mma convs
__global__ void genw_bf16_kernel(const float* __restrict__ w, const float* __restrict__ bias,
                                 const int* __restrict__ action, uint2* __restrict__ out, int CIN,
                                 int NCH, int COUT) {
    int i = blockIdx.x * 256 + threadIdx.x;
    int total = 16 * NCH * 25 * 8 * COUT;
    if (i >= total) return;
    int co = i % COUT;
    int r = i / COUT;
    int kp = r % 8;
    r /= 8;
    int tap = r % 25;
    r /= 25;
    int chv = r % NCH;
    int b = r / NCH;
    int a = action[b];
    int ci0 = chv * 16 + kp * 2;
    float v0 = 0.f, v1 = 0.f;
    if (ci0 < CIN) {
        int o = (co * CIN + ci0) * 25 + tap;
        v0 = w[o * 6 + a] + bias[o];
    }
    if (ci0 + 1 < CIN) {
        int o = (co * CIN + ci0 + 1) * 25 + tap;
        v1 = w[o * 6 + a] + bias[o];
    }
    out[i] = bsplit2(v0, v1);
}

// ---------------- per-(b,c) BN stats -> affine (scale,bias) ----------------
template <int N>
__global__ void stats_kernel(const float* __restrict__ in, const float* __restrict__ s,
                             const float* __restrict__ bb, float* __restrict__ aff, int C) {
    int bc = blockIdx.x;  // b*C + c
    const float* p = in + (size_t)bc * N;
    float sum = 0.f, sq = 0.f;
    for (int i = threadIdx.x; i < N; i += 256) {
        float v = p[i];
        sum += v;
        sq += v * v;
    }
    __shared__ float ssum[256], ssq[256];
    ssum[threadIdx.x] = sum;
    ssq[threadIdx.x] = sq;
    __syncthreads();
    for (int st = 128; st > 0; st >>= 1) {
        if (threadIdx.x < st) {
            ssum[threadIdx.x] += ssum[threadIdx.x + st];
            ssq[threadIdx.x] += ssq[threadIdx.x + st];
        }
        __syncthreads();
    }
    if (threadIdx.x == 0) {
        int c = bc % C;
        float mean = ssum[0] / (float)N;
        float var = ssq[0] / (float)N - mean * mean;
        float sc = rsqrtf(var + EPS) * s[c];
        aff[2 * bc] = sc;
        aff[2 * bc + 1] = bb[c] - mean * sc;
    }
}

// ---------------- bf16x3 tensor-core 5x5 conv (per-tap implicit GEMM) ----------------
// 256 threads (8 warps). Output tile: 32 x TH pixels, COUT_B output channels.
// hi/lo bf16 pairs packed in uint2; 3 mmas (hh, hl, lh) per k16 per tile.
template <int CIN, int COUT, int COUT_B, int H, int DIL, int TH, bool AFF, bool RELU>
__global__ __launch_bounds__(256, 2) void conv5_bf16_kernel(const float* __restrict__ in,
                                                            const float* __restrict__ aff,
                                                            const uint2* __restrict__ wts,
                                                            float* __restrict__ out) {
    constexpr int R = 2 * DIL;
    constexpr int PX = 32 + 2 * R;
    constexpr int PY = TH + 2 * R;
    constexpr int PLANE0 = PX * PY;
    constexpr int PS = PLANE0 + ((4 - PLANE0 % 16) + 16) % 16;  // ≡4 (mod 16) u2 units
    constexpr int WS = COUT_B + 4;
    constexpr int NT = COUT_B / 8;
    constexpr int MT = (TH / 8) * 2;
    constexpr int RPW = TH / 8;
    constexpr int CGRP = COUT / COUT_B;
    constexpr int CINPAD = (CIN + 15) & ~15;
    constexpr int NCH = CINPAD / 16;

    extern __shared__ uint2 sm[];
    uint2* wtile = sm;                // [25][8][WS]
    uint2* patch = sm + 25 * 8 * WS;  // [8 pairs][PS]

    int tid = threadIdx.x, wid = tid >> 5, lane = tid & 31;
    int tg = lane & 3, gid = lane >> 2;
    int bx0 = blockIdx.x * 32;
    int ytile = blockIdx.y / CGRP;
    int cg = blockIdx.y % CGRP;
    int by0 = ytile * TH;
    int b = blockIdx.z;
    int co0 = cg * COUT_B;

    const float* inb = in + (size_t)b * CIN * H * H;
    const float* affb = aff + b * CIN * 2;
    const uint2* wb = wts + ((size_t)b * NCH * 25 * 8) * COUT + co0;

    float acc[MT][NT][4];
#pragma unroll
    for (int mt = 0; mt < MT; mt++)
#pragma unroll
        for (int nt = 0; nt < NT; nt++)
#pragma unroll
            for (int k = 0; k < 4; k++) acc[mt][nt][k] = 0.f;

    int baseA[MT];
#pragma unroll
    for (int mt = 0; mt < MT; mt++) {
        int rofs = (MT == 4) ? (mt >> 1) : 0;
        int pxo = ((MT == 4) ? (mt & 1) : mt) * 16;
        baseA[mt] = tg * PS + (wid * RPW + rofs) * PX + pxo + gid;
    }

    for (int ch = 0; ch < NCH; ch++) {
        __syncthreads();
        // ---- load 16-channel patch (8 hi/lo channel-pair planes) ----
        for (int idx = tid; idx < 8 * PLANE0; idx += 256) {
            int p = idx / PLANE0;
            int rem = idx - p * PLANE0;
            int py = rem / PX, px = rem - py * PX;
            int gy = by0 - R + py, gx = bx0 - R + px;
            int c0 = ch * 16 + 2 * p;
            float v0 = 0.f, v1 = 0.f;
            if ((unsigned)gy < (unsigned)H && (unsigned)gx < (unsigned)H) {
                if (c0 < CIN) {
                    v0 = inb[((size_t)c0 * H + gy) * H + gx];
                    if (AFF) {
                        v0 = fmaf(v0, __ldg(affb + 2 * c0), __ldg(affb + 2 * c0 + 1));
                        if (RELU) v0 = fmaxf(v0, 0.f);
                    }
                }
                if (c0 + 1 < CIN) {
                    v1 = inb[((size_t)(c0 + 1) * H + gy) * H + gx];
                    if (AFF) {
                        v1 = fmaf(v1, __ldg(affb + 2 * c0 + 2), __ldg(affb + 2 * c0 + 3));
                        if (RELU) v1 = fmaxf(v1, 0.f);
                    }
                }
            }
            patch[p * PS + py * PX + px] = bsplit2(v0, v1);
        }
        // ---- stage all 25 taps of weights for this chunk ----
        const uint2* wc = wb + (size_t)ch * 25 * 8 * COUT;
        for (int idx = tid; idx < 25 * 8 * COUT_B; idx += 256) {
            int t8 = idx / COUT_B;
            int co = idx - t8 * COUT_B;
            wtile[t8 * WS + co] = wc[(size_t)t8 * COUT + co];
        }
        __syncthreads();

#pragma unroll
        for (int ky = 0; ky < 5; ky++) {
#pragma unroll
            for (int kx = 0; kx < 5; kx++) {
                const uint2* wt = wtile + (ky * 5 + kx) * 8 * WS;
                uint2 Bf[NT][2];
#pragma unroll
                for (int nt = 0; nt < NT; nt++) {
                    Bf[nt][0] = wt[tg * WS + nt * 8 + gid];
                    Bf[nt][1] = wt[(tg + 4) * WS + nt * 8 + gid];
                }
#pragma unroll
                for (int mt = 0; mt < MT; mt++) {
                    int ao = baseA[mt] + ky * DIL * PX + kx * DIL;
                    uint2 A0 = patch[ao];
                    uint2 A1 = patch[ao + 8];
                    uint2 A2 = patch[ao + 4 * PS];
                    uint2 A3 = patch[ao + 4 * PS + 8];
#pragma unroll
                    for (int nt = 0; nt < NT; nt++) {
                        mma_bf16(acc[mt][nt], A0.x, A1.x, A2.x, A3.x, Bf[nt][0].x, Bf[nt][1].x);
                        mma_bf16(acc[mt][nt], A0.x, A1.x, A2.x, A3.x, Bf[nt][0].y, Bf[nt][1].y);
                        mma_bf16(acc[mt][nt], A0.y, A1.y, A2.y, A3.y, Bf[nt][0].x, Bf[nt][1].x);
                    }
                }
            }
        }
    }

    // ---- epilogue ----
#pragma unroll
    for (int mt = 0; mt < MT; mt++) {
        int rofs = (MT == 4) ? (mt >> 1) : 0;
        int pxo = ((MT == 4) ? (mt & 1) : mt) * 16;
        int gy = by0 + wid * RPW + rofs;
        int gx = bx0 + pxo + gid;
#pragma unroll
        for (int nt = 0; nt < NT; nt++) {
            int co = co0 + nt * 8 + 2 * tg;
            float* o = out + ((size_t)(b * COUT + co) * H + gy) * H;
            o[gx] = acc[mt][nt][0];
            o[(size_t)H * H + gx] = acc[mt][nt][1];
            o[gx + 8] = acc[mt][nt][2];
            o[(size_t)H * H + gx + 8] = acc[mt][nt][3];
        }
    }
}

// ---------------- 2x2 avgpool fused with BN2 affine ----------------
__global__ void avgpool_kernel(const float* __restrict__ in, const float* __restrict__ aff,
                               float* __restrict__ out) {
    int idx = blockIdx.x * 256 + threadIdx.x;
    if (idx >= 16 * 16 * 128 * 128) return;
    int x = idx & 127;
    int y = (idx >> 7) & 127;
    int bc = idx >> 14;  // b*16 + c
    const float* p = in + ((size_t)bc * 256 + 2 * y) * 256 + 2 * x;
    float sc = aff[2 * bc], bi = aff[2 * bc + 1];
    float s = p[0] + p[1] + p[256] + p[257];
    out[idx] = fmaf(s * 0.25f, sc, bi);
}

// ---------------- 1x1 conv (64->4), BN6 affine fused on input ----------------
__global__ __launch_bounds__(256) void conv1x1_kernel(const float* __restrict__ in,
                                                      const float* __restrict__ aff,
                                                      const float* __restrict__ wts,
                                                      float* __restrict__ out) {
    int b = blockIdx.y;
    int p = blockIdx.x * 256 + threadIdx.x;  // pixel 0..16383
    __shared__ float wsh[4][64];
    __shared__ float sc[64], bi[64];
    int tid = threadIdx.x;
    wsh[tid >> 6][tid & 63] = wts[b * 256 + tid];
    if (tid < 64) {
        sc[tid] = aff[(b * 64 + tid) * 2];
        bi[tid] = aff[(b * 64 + tid) * 2 + 1];
    }
    __syncthreads();
    float acc[4] = {0.f, 0.f, 0.f, 0.f};
    const float* pin = in + (size_t)b * 64 * 16384 + p;
#pragma unroll 8
    for (int ci = 0; ci < 64; ci++) {
        float v = fmaf(pin[(size_t)ci * 16384], sc[ci], bi[ci]);
#pragma unroll
        for (int co = 0; co < 4; co++) acc[co] = fmaf(v, wsh[co][ci], acc[co]);
    }
#pragma unroll
    for (int co = 0; co < 4; co++) out[((size_t)b * 4 + co) * 16384 + p] = acc[co];
}

// ---------------- bilinear x2 (align_corners) + residual add ----------------
__global__ void up_add_kernel(const float* __restrict__ in, const float* __restrict__ x,
                              float* __restrict__ out) {
    int idx = blockIdx.x * 256 + threadIdx.x;
    if (idx >= 16 * 4 * 256 * 256) return;
    int ox = idx & 255;
    int oy = (idx >> 8) & 255;
    int bc = idx >> 16;  // b*4 + c
    const float r = (float)(127.0 / 255.0);
    float px = ox * r, py = oy * r;
    int x0 = (int)px, y0 = (int)py;
    float fx = px - x0, fy = py - y0;
    int x1 = min(x0 + 1, 127), y1 = min(y0 + 1, 127);
    const float* p = in + (size_t)bc * 16384;
    float v00 = p[y0 * 128 + x0], v01 = p[y0 * 128 + x1];
    float v10 = p[y1 * 128 + x0], v11 = p[y1 * 128 + x1];
    float v0 = v00 * (1.f - fx) + v01 * fx;
    float v1 = v10 * (1.f - fx) + v11 * fx;
    out[idx] = v0 * (1.f - fy) + v1 * fy + x[idx];
}

// ---------------- host-side smem size mirror ----------------
static int smem_bytes(int COUT_B, int DIL, int TH) {
    int R = 2 * DIL;
    int PX = 32 + 2 * R, PY = TH + 2 * R;
    int PLANE0 = PX * PY;
    int PS = PLANE0 + ((4 - PLANE0 % 16) + 16) % 16;
    return (25 * 8 * (COUT_B + 4) + 8 * PS) * 8;
}

// ---------------- launch ----------------
extern "C" void kernel_launch(void* const* d_in, const int* in_sizes, int n_in,
                              void* d_out, int out_size) {
    const float* x = (const float*)d_in[0];
    const int* action = (const int*)d_in[1];
    const float* w[7];
    const float* wb[7];
    for (int i = 0; i < 7; i++) {
        w[i] = (const float*)d_in[2 + 2 * i];
        wb[i] = (const float*)d_in[3 + 2 * i];
    }
    const float* bns[7];
    const float* bnb[7];
    for (int i = 0; i < 7; i++) {
        bns[i] = (const float*)d_in[16 + 2 * i];
        bnb[i] = (const float*)d_in[17 + 2 * i];
    }

    uint2 *k1, *k2, *k3, *k4, *k5, *k6;
    float* k7;
    float *t1, *t2, *t3, *t4, *t5, *t6, *t7, *t8, *aff;
    cudaGetSymbolAddress((void**)&k1, g_k1);
    cudaGetSymbolAddress((void**)&k2, g_k2);
    cudaGetSymbolAddress((void**)&k3, g_k3);
    cudaGetSymbolAddress((void**)&k4, g_k4);
    cudaGetSymbolAddress((void**)&k5, g_k5);
    cudaGetSymbolAddress((void**)&k6, g_k6);
    cudaGetSymbolAddress((void**)&k7, g_k7);
    cudaGetSymbolAddress((void**)&t1, g_t1);
    cudaGetSymbolAddress((void**)&t2, g_t2);
    cudaGetSymbolAddress((void**)&t3, g_t3);
    cudaGetSymbolAddress((void**)&t4, g_t4);
    cudaGetSymbolAddress((void**)&t5, g_t5);
    cudaGetSymbolAddress((void**)&t6, g_t6);
    cudaGetSymbolAddress((void**)&t7, g_t7);
    cudaGetSymbolAddress((void**)&t8, g_t8);
    cudaGetSymbolAddress((void**)&aff, g_aff);

    const int AOFF = 16 * 64 * 2;

    // opt-in dynamic smem (idempotent)
    cudaFuncSetAttribute(conv5_bf16_kernel<4, 16, 16, 256, 2, 8, true, false>,
                         cudaFuncAttributeMaxDynamicSharedMemorySize, smem_bytes(16, 2, 8));
    cudaFuncSetAttribute(conv5_bf16_kernel<16, 16, 16, 256, 1, 16, true, true>,
                         cudaFuncAttributeMaxDynamicSharedMemorySize, smem_bytes(16, 1, 16));
    cudaFuncSetAttribute(conv5_bf16_kernel<16, 32, 32, 128, 2, 8, false, false>,
                         cudaFuncAttributeMaxDynamicSharedMemorySize, smem_bytes(32, 2, 8));
    cudaFuncSetAttribute(conv5_bf16_kernel<32, 32, 32, 128, 1, 16, true, true>,
                         cudaFuncAttributeMaxDynamicSharedMemorySize, smem_bytes(32, 1, 16));
    cudaFuncSetAttribute(conv5_bf16_kernel<32, 64, 32, 128, 2, 8, true, false>,
                         cudaFuncAttributeMaxDynamicSharedMemorySize, smem_bytes(32, 2, 8));
    cudaFuncSetAttribute(conv5_bf16_kernel<64, 64, 32, 128, 1, 16, true, true>,
                         cudaFuncAttributeMaxDynamicSharedMemorySize, smem_bytes(32, 1, 16));

    // generate per-batch conv kernels (bf16 hi/lo split, mma layout)
    {
        int t;
        t = 16 * 1 * 25 * 8 * 16;
        genw_bf16_kernel<<<(t + 255) / 256, 256>>>(w[0], wb[0], action, k1, 4, 1, 16);
        genw_bf16_kernel<<<(t + 255) / 256, 256>>>(w[1], wb[1], action, k2, 16, 1, 16);
        t = 16 * 1 * 25 * 8 * 32;
        genw_bf16_kernel<<<(t + 255) / 256, 256>>>(w[2], wb[2], action, k3, 16, 1, 32);
        t = 16 * 2 * 25 * 8 * 32;
        genw_bf16_kernel<<<(t + 255) / 256, 256>>>(w[3], wb[3], action, k4, 32, 2, 32);
        t = 16 * 2 * 25 * 8 * 64;
        genw_bf16_kernel<<<(t + 255) / 256, 256>>>(w[4], wb[4], action, k5, 32, 2, 64);
        t = 16 * 4 * 25 * 8 * 64;
        genw_bf16_kernel<<<(t + 255) / 256, 256>>>(w[5], wb[5], action, k6, 64, 4, 64);
    }
    genw_kernel<<<(256 * 16 + 255) / 256, 256>>>(w[6], wb[6], action, k7, 256);

    // bn0 stats on x
    stats_kernel<65536><<<16 * 4, 256>>>(x, bns[0], bnb[0], aff + 0 * AOFF, 4);
    // conv1: bn0(x) -> t1
    conv5_bf16_kernel<4, 16, 16, 256, 2, 8, true, false>
        <<<dim3(8, 32, 16), 256, smem_bytes(16, 2, 8)>>>(x, aff + 0 * AOFF, k1, t1);
    // bn1 stats
    stats_kernel<65536><<<16 * 16, 256>>>(t1, bns[1], bnb[1], aff + 1 * AOFF, 16);
    // conv2: relu(bn1(t1)) -> t2
    conv5_bf16_kernel<16, 16, 16, 256, 1, 16, true, true>
        <<<dim3(8, 16, 16), 256, smem_bytes(16, 1, 16)>>>(t1, aff + 1 * AOFF, k2, t2);
    // bn2 stats
    stats_kernel<65536><<<16 * 16, 256>>>(t2, bns[2], bnb[2], aff + 2 * AOFF, 16);
    // avgpool(bn2(t2)) -> t3 (normalized)
    avgpool_kernel<<<(16 * 16 * 128 * 128 + 255) / 256, 256>>>(t2, aff + 2 * AOFF, t3);
    // conv3: t3 -> t4
    conv5_bf16_kernel<16, 32, 32, 128, 2, 8, false, false>
        <<<dim3(4, 16, 16), 256, smem_bytes(32, 2, 8)>>>(t3, aff, k3, t4);
    // bn3 stats
    stats_kernel<16384><<<16 * 32, 256>>>(t4, bns[3], bnb[3], aff + 3 * AOFF, 32);
    // conv4: relu(bn3(t4)) -> t5
    conv5_bf16_kernel<32, 32, 32, 128, 1, 16, true, true>
        <<<dim3(4, 8, 16), 256, smem_bytes(32, 1, 16)>>>(t4, aff + 3 * AOFF, k4, t5);
    // bn4 stats
    stats_kernel<16384><<<16 * 32, 256>>>(t5, bns[4], bnb[4], aff + 4 * AOFF, 32);
    // conv5: bn4(t5) -> t6
    conv5_bf16_kernel<32, 64, 32, 128, 2, 8, true, false>
        <<<dim3(4, 32, 16), 256, smem_bytes(32, 2, 8)>>>(t5, aff + 4 * AOFF, k5, t6);
    // bn5 stats
    stats_kernel<16384><<<16 * 64, 256>>>(t6, bns[5], bnb[5], aff + 5 * AOFF, 64);
    // conv6: relu(bn5(t6)) -> t7
    conv5_bf16_kernel<64, 64, 32, 128, 1, 16, true, true>
        <<<dim3(4, 16, 16), 256, smem_bytes(32, 1, 16)>>>(t6, aff + 5 * AOFF, k6, t7);
    // bn6 stats
    stats_kernel<16384><<<16 * 64, 256>>>(t7, bns[6], bnb[6], aff + 6 * AOFF, 64);
    // conv7 1x1: bn6(t7) -> t8
    conv1x1_kernel<<<dim3(64, 16), 256>>>(t7, aff + 6 * AOFF, k7, t8);
    // upsample + residual
    up_add_kernel<<<(16 * 4 * 256 * 256 + 255) / 256, 256>>>(t8, x, (float*)d_out);
}

// round 6
// speedup vs baseline: 1.0057x; 1.0057x over previous
#include <cuda_runtime.h>
#include <cuda_bf16.h>
#include <cstdint>

#define EPS 1e-5f

// ---------------- scratch (static __device__ — no allocation) ----------------
// conv weights in bf16-split u2 layout: [b][chunk(CINPAD/16)][tap(25)][kpair(8)][COUT]
__device__ uint2 g_k1[16 * 1 * 25 * 8 * 16];
__device__ uint2 g_k2[16 * 1 * 25 * 8 * 16];
__device__ uint2 g_k3[16 * 1 * 25 * 8 * 32];
__device__ uint2 g_k4[16 * 2 * 25 * 8 * 32];
__device__ uint2 g_k5[16 * 2 * 25 * 8 * 64];
__device__ uint2 g_k6[16 * 4 * 25 * 8 * 64];
__device__ float g_k7[16 * 4 * 64];

__device__ float g_t1[16 * 16 * 256 * 256];
__device__ float g_t2[16 * 16 * 256 * 256];
__device__ float g_t3[16 * 16 * 128 * 128];
__device__ float g_t4[16 * 32 * 128 * 128];
__device__ float g_t5[16 * 32 * 128 * 128];
__device__ float g_t6[16 * 64 * 128 * 128];
__device__ float g_t7[16 * 64 * 128 * 128];
__device__ float g_t8[16 * 4 * 128 * 128];

// per-layer BN affine: [layer][b*C + c][2] ; max C = 64
__device__ float g_aff[7 * 16 * 64 * 2];

// ---------------- helpers ----------------
__device__ __forceinline__ uint2 bsplit2(float v0, float v1) {
    __nv_bfloat16 h0 = __float2bfloat16(v0);
    __nv_bfloat16 h1 = __float2bfloat16(v1);
    float l0 = v0 - __bfloat162float(h0);
    float l1 = v1 - __bfloat162float(h1);
    __nv_bfloat162 hi, lo;
    hi.x = h0;
    hi.y = h1;
    lo.x = __float2bfloat16(l0);
    lo.y = __float2bfloat16(l1);
    uint2 u;
    u.x = *reinterpret_cast<uint32_t*>(&hi);
    u.y = *reinterpret_cast<uint32_t*>(&lo);
    return u;
}

__device__ __forceinline__ void mma_bf16(float c[4], uint32_t a0, uint32_t a1, uint32_t a2,
                                         uint32_t a3, uint32_t b0, uint32_t b1) {
    asm volatile(
        "mma.sync.aligned.m16n8k16.row.col.f32.bf16.bf16.f32 "
        "{%0,%1,%2,%3},{%4,%5,%6,%7},{%8,%9},{%0,%1,%2,%3};"
        : "+f"(c[0]), "+f"(c[1]), "+f"(c[2]), "+f"(c[3])
        : "r"(a0), "r"(a1), "r"(a2), "r"(a3), "r"(b0), "r"(b1));
}

// ---------------- per-batch weight generation ----------------
// plain fp32 layout (for 1x1 conv)
__global__ void genw_kernel(const float* __restrict__ w, const float* __restrict__ bias,
                            const int* __restrict__ action, float* __restrict__ out, int od) {
    int i = blockIdx.x * blockDim.x + threadIdx.x;
    int total = od * 16;
    if (i >= total) return;
    int b = i / od, o = i - b * od;
    out[i] = w[o * 6 + action[b]] + bias[o];
}

// bf16-split u2 layout for mma convs
__global__ void genw_bf16_kernel(const float* __restrict__ w, const float* __restrict__ bias,
                                 const int* __restrict__ action, uint2* __restrict__ out, int CIN,
                                 int NCH, int COUT) {
    int i = blockIdx.x * 256 + threadIdx.x;
    int total = 16 * NCH * 25 * 8 * COUT;
    if (i >= total) return;
    int co = i % COUT;
    int r = i / COUT;
    int kp = r % 8;
    r /= 8;
    int tap = r % 25;
    r /= 25;
    int chv = r % NCH;
    int b = r / NCH;
    int a = action[b];
    int ci0 = chv * 16 + kp * 2;
    float v0 = 0.f, v1 = 0.f;
    if (ci0 < CIN) {
        int o = (co * CIN + ci0) * 25 + tap;
        v0 = w[o * 6 + a] + bias[o];
    }
    if (ci0 + 1 < CIN) {
        int o = (co * CIN + ci0 + 1) * 25 + tap;
        v1 = w[o * 6 + a] + bias[o];
    }
    out[i] = bsplit2(v0, v1);
}

// ---------------- per-(b,c) BN stats -> affine (scale,bias) ----------------
template <int N>
__global__ void stats_kernel(const float* __restrict__ in, const float* __restrict__ s,
                             const float* __restrict__ bb, float* __restrict__ aff, int C) {
    int bc = blockIdx.x;  // b*C + c
    const float* p = in + (size_t)bc * N;
    float sum = 0.f, sq = 0.f;
    for (int i = threadIdx.x; i < N; i += 256) {
        float v = p[i];
        sum += v;
        sq += v * v;
    }
    __shared__ float ssum[256], ssq[256];
    ssum[threadIdx.x] = sum;
    ssq[threadIdx.x] = sq;
    __syncthreads();
    for (int st = 128; st > 0; st >>= 1) {
        if (threadIdx.x < st) {
            ssum[threadIdx.x] += ssum[threadIdx.x + st];
            ssq[threadIdx.x] += ssq[threadIdx.x + st];
        }
        __syncthreads();
    }
    if (threadIdx.x == 0) {
        int c = bc % C;
        float mean = ssum[0] / (float)N;
        float var = ssq[0] / (float)N - mean * mean;
        float sc = rsqrtf(var + EPS) * s[c];
        aff[2 * bc] = sc;
        aff[2 * bc + 1] = bb[c] - mean * sc;
    }
}

// ---------------- bf16x3 tensor-core 5x5 conv (per-tap implicit GEMM) ----------------
// 256 threads (8 warps). Output tile: 32 x TH pixels, COUT_B output channels.
// hi/lo bf16 pairs packed in uint2; 3 mmas (hh, hl, lh) per k16 per tile.
template <int CIN, int COUT, int COUT_B, int H, int DIL, int TH, bool AFF, bool RELU>
__global__ __launch_bounds__(256, 2) void conv5_bf16_kernel(const float* __restrict__ in,
                                                            const float* __restrict__ aff,
                                                            const uint2* __restrict__ wts,
                                                            float* __restrict__ out) {
    constexpr int R = 2 * DIL;
    constexpr int PX = 32 + 2 * R;
    constexpr int PY = TH + 2 * R;
    constexpr int PLANE0 = PX * PY;
    constexpr int PS = PLANE0 + ((4 - PLANE0 % 16) + 16) % 16;  // ≡4 (mod 16) u2 units
    constexpr int WS = COUT_B + 4;
    constexpr int NT = COUT_B / 8;
    constexpr int MT = (TH / 8) * 2;
    constexpr int RPW = TH / 8;
    constexpr int CGRP = COUT / COUT_B;
    constexpr int CINPAD = (CIN + 15) & ~15;
    constexpr int NCH = CINPAD / 16;

    extern __shared__ uint2 sm[];
    uint2* wtile = sm;                // [25][8][WS]
    uint2* patch = sm + 25 * 8 * WS;  // [8 pairs][PS]

    int tid = threadIdx.x, wid = tid >> 5, lane = tid & 31;
    int tg = lane & 3, gid = lane >> 2;
    int bx0 = blockIdx.x * 32;
    int ytile = blockIdx.y / CGRP;
    int cg = blockIdx.y % CGRP;
    int by0 = ytile * TH;
    int b = blockIdx.z;
    int co0 = cg * COUT_B;

    const float* inb = in + (size_t)b * CIN * H * H;
    const float* affb = aff + b * CIN * 2;
    const uint2* wb = wts + ((size_t)b * NCH * 25 * 8) * COUT + co0;

    float acc[MT][NT][4];
#pragma unroll
    for (int mt = 0; mt < MT; mt++)
#pragma unroll
        for (int nt = 0; nt < NT; nt++)
#pragma unroll
            for (int k = 0; k < 4; k++) acc[mt][nt][k] = 0.f;

    int baseA[MT];
#pragma unroll
    for (int mt = 0; mt < MT; mt++) {
        int rofs = (MT == 4) ? (mt >> 1) : 0;
        int pxo = ((MT == 4) ? (mt & 1) : mt) * 16;
        baseA[mt] = tg * PS + (wid * RPW + rofs) * PX + pxo + gid;
    }

    for (int ch = 0; ch < NCH; ch++) {
        __syncthreads();
        // ---- load 16-channel patch (8 hi/lo channel-pair planes) ----
        for (int idx = tid; idx < 8 * PLANE0; idx += 256) {
            int p = idx / PLANE0;
            int rem = idx - p * PLANE0;
            int py = rem / PX, px = rem - py * PX;
            int gy = by0 - R + py, gx = bx0 - R + px;
            int c0 = ch * 16 + 2 * p;
            float v0 = 0.f, v1 = 0.f;
            if ((unsigned)gy < (unsigned)H && (unsigned)gx < (unsigned)H) {
                if (c0 < CIN) {
                    v0 = inb[((size_t)c0 * H + gy) * H + gx];
                    if (AFF) {
                        v0 = fmaf(v0, __ldg(affb + 2 * c0), __ldg(affb + 2 * c0 + 1));
                        if (RELU) v0 = fmaxf(v0, 0.f);
                    }
                }
                if (c0 + 1 < CIN) {
                    v1 = inb[((size_t)(c0 + 1) * H + gy) * H + gx];
                    if (AFF) {
                        v1 = fmaf(v1, __ldg(affb + 2 * c0 + 2), __ldg(affb + 2 * c0 + 3));
                        if (RELU) v1 = fmaxf(v1, 0.f);
                    }
                }
            }
            patch[p * PS + py * PX + px] = bsplit2(v0, v1);
        }
        // ---- stage all 25 taps of weights for this chunk ----
        const uint2* wc = wb + (size_t)ch * 25 * 8 * COUT;
        for (int idx = tid; idx < 25 * 8 * COUT_B; idx += 256) {
            int t8 = idx / COUT_B;
            int co = idx - t8 * COUT_B;
            wtile[t8 * WS + co] = wc[(size_t)t8 * COUT + co];
        }
        __syncthreads();

#pragma unroll
        for (int ky = 0; ky < 5; ky++) {
#pragma unroll
            for (int kx = 0; kx < 5; kx++) {
                const uint2* wt = wtile + (ky * 5 + kx) * 8 * WS;
                uint2 Bf[NT][2];
#pragma unroll
                for (int nt = 0; nt < NT; nt++) {
                    Bf[nt][0] = wt[tg * WS + nt * 8 + gid];
                    Bf[nt][1] = wt[(tg + 4) * WS + nt * 8 + gid];
                }
#pragma unroll
                for (int mt = 0; mt < MT; mt++) {
                    int ao = baseA[mt] + ky * DIL * PX + kx * DIL;
                    uint2 A0 = patch[ao];
                    uint2 A1 = patch[ao + 8];
                    uint2 A2 = patch[ao + 4 * PS];
                    uint2 A3 = patch[ao + 4 * PS + 8];
#pragma unroll
                    for (int nt = 0; nt < NT; nt++) {
                        mma_bf16(acc[mt][nt], A0.x, A1.x, A2.x, A3.x, Bf[nt][0].x, Bf[nt][1].x);
                        mma_bf16(acc[mt][nt], A0.x, A1.x, A2.x, A3.x, Bf[nt][0].y, Bf[nt][1].y);
                        mma_bf16(acc[mt][nt], A0.y, A1.y, A2.y, A3.y, Bf[nt][0].x, Bf[nt][1].x);
                    }
                }
            }
        }
    }

    // ---- epilogue ----
#pragma unroll
    for (int mt = 0; mt < MT; mt++) {
        int rofs = (MT == 4) ? (mt >> 1) : 0;
        int pxo = ((MT == 4) ? (mt & 1) : mt) * 16;
        int gy = by0 + wid * RPW + rofs;
        int gx = bx0 + pxo + gid;
#pragma unroll
        for (int nt = 0; nt < NT; nt++) {
            int co = co0 + nt * 8 + 2 * tg;
            float* o = out + ((size_t)(b * COUT + co) * H + gy) * H;
            o[gx] = acc[mt][nt][0];
            o[(size_t)H * H + gx] = acc[mt][nt][1];
            o[gx + 8] = acc[mt][nt][2];
            o[(size_t)H * H + gx + 8] = acc[mt][nt][3];
        }
    }
}

// ---------------- 2x2 avgpool fused with BN2 affine ----------------
__global__ void avgpool_kernel(const float* __restrict__ in, const float* __restrict__ aff,
                               float* __restrict__ out) {
    int idx = blockIdx.x * 256 + threadIdx.x;
    if (idx >= 16 * 16 * 128 * 128) return;
    int x = idx & 127;
    int y = (idx >> 7) & 127;
    int bc = idx >> 14;  // b*16 + c
    const float* p = in + ((size_t)bc * 256 + 2 * y) * 256 + 2 * x;
    float sc = aff[2 * bc], bi = aff[2 * bc + 1];
    float s = p[0] + p[1] + p[256] + p[257];
    out[idx] = fmaf(s * 0.25f, sc, bi);
}

// ---------------- 1x1 conv (64->4), BN6 affine fused on input ----------------
__global__ __launch_bounds__(256) void conv1x1_kernel(const float* __restrict__ in,
                                                      const float* __restrict__ aff,
                                                      const float* __restrict__ wts,
                                                      float* __restrict__ out) {
    int b = blockIdx.y;
    int p = blockIdx.x * 256 + threadIdx.x;  // pixel 0..16383
    __shared__ float wsh[4][64];
    __shared__ float sc[64], bi[64];
    int tid = threadIdx.x;
    wsh[tid >> 6][tid & 63] = wts[b * 256 + tid];
    if (tid < 64) {
        sc[tid] = aff[(b * 64 + tid) * 2];
        bi[tid] = aff[(b * 64 + tid) * 2 + 1];
    }
    __syncthreads();
    float acc[4] = {0.f, 0.f, 0.f, 0.f};
    const float* pin = in + (size_t)b * 64 * 16384 + p;
#pragma unroll 8
    for (int ci = 0; ci < 64; ci++) {
        float v = fmaf(pin[(size_t)ci * 16384], sc[ci], bi[ci]);
#pragma unroll
        for (int co = 0; co < 4; co++) acc[co] = fmaf(v, wsh[co][ci], acc[co]);
    }
#pragma unroll
    for (int co = 0; co < 4; co++) out[((size_t)b * 4 + co) * 16384 + p] = acc[co];
}

// ---------------- bilinear x2 (align_corners) + residual add ----------------
__global__ void up_add_kernel(const float* __restrict__ in, const float* __restrict__ x,
                              float* __restrict__ out) {
    int idx = blockIdx.x * 256 + threadIdx.x;
    if (idx >= 16 * 4 * 256 * 256) return;
    int ox = idx & 255;
    int oy = (idx >> 8) & 255;
    int bc = idx >> 16;  // b*4 + c
    const float r = (float)(127.0 / 255.0);
    float px = ox * r, py = oy * r;
    int x0 = (int)px, y0 = (int)py;
    float fx = px - x0, fy = py - y0;
    int x1 = min(x0 + 1, 127), y1 = min(y0 + 1, 127);
    const float* p = in + (size_t)bc * 16384;
    float v00 = p[y0 * 128 + x0], v01 = p[y0 * 128 + x1];
    float v10 = p[y1 * 128 + x0], v11 = p[y1 * 128 + x1];
    float v0 = v00 * (1.f - fx) + v01 * fx;
    float v1 = v10 * (1.f - fx) + v11 * fx;
    out[idx] = v0 * (1.f - fy) + v1 * fy + x[idx];
}

// ---------------- host-side smem size mirror ----------------
static int smem_bytes(int COUT_B, int DIL, int TH) {
    int R = 2 * DIL;
    int PX = 32 + 2 * R, PY = TH + 2 * R;
    int PLANE0 = PX * PY;
    int PS = PLANE0 + ((4 - PLANE0 % 16) + 16) % 16;
    return (25 * 8 * (COUT_B + 4) + 8 * PS) * 8;
}

// ---------------- launch ----------------
extern "C" void kernel_launch(void* const* d_in, const int* in_sizes, int n_in,
                              void* d_out, int out_size) {
    const float* x = (const float*)d_in[0];
    const int* action = (const int*)d_in[1];
    const float* w[7];
    const float* wb[7];
    for (int i = 0; i < 7; i++) {
        w[i] = (const float*)d_in[2 + 2 * i];
        wb[i] = (const float*)d_in[3 + 2 * i];
    }
    const float* bns[7];
    const float* bnb[7];
    for (int i = 0; i < 7; i++) {
        bns[i] = (const float*)d_in[16 + 2 * i];
        bnb[i] = (const float*)d_in[17 + 2 * i];
    }

    uint2 *k1, *k2, *k3, *k4, *k5, *k6;
    float* k7;
    float *t1, *t2, *t3, *t4, *t5, *t6, *t7, *t8, *aff;
    cudaGetSymbolAddress((void**)&k1, g_k1);
    cudaGetSymbolAddress((void**)&k2, g_k2);
    cudaGetSymbolAddress((void**)&k3, g_k3);
    cudaGetSymbolAddress((void**)&k4, g_k4);
    cudaGetSymbolAddress((void**)&k5, g_k5);
    cudaGetSymbolAddress((void**)&k6, g_k6);
    cudaGetSymbolAddress((void**)&k7, g_k7);
    cudaGetSymbolAddress((void**)&t1, g_t1);
    cudaGetSymbolAddress((void**)&t2, g_t2);
    cudaGetSymbolAddress((void**)&t3, g_t3);
    cudaGetSymbolAddress((void**)&t4, g_t4);
    cudaGetSymbolAddress((void**)&t5, g_t5);
    cudaGetSymbolAddress((void**)&t6, g_t6);
    cudaGetSymbolAddress((void**)&t7, g_t7);
    cudaGetSymbolAddress((void**)&t8, g_t8);
    cudaGetSymbolAddress((void**)&aff, g_aff);

    const int AOFF = 16 * 64 * 2;

    // opt-in dynamic smem (idempotent)
    cudaFuncSetAttribute(conv5_bf16_kernel<4, 16, 16, 256, 2, 8, true, false>,
                         cudaFuncAttributeMaxDynamicSharedMemorySize, smem_bytes(16, 2, 8));
    cudaFuncSetAttribute(conv5_bf16_kernel<16, 16, 16, 256, 1, 16, true, true>,
                         cudaFuncAttributeMaxDynamicSharedMemorySize, smem_bytes(16, 1, 16));
    cudaFuncSetAttribute(conv5_bf16_kernel<16, 32, 32, 128, 2, 8, false, false>,
                         cudaFuncAttributeMaxDynamicSharedMemorySize, smem_bytes(32, 2, 8));
    cudaFuncSetAttribute(conv5_bf16_kernel<32, 32, 32, 128, 1, 16, true, true>,
                         cudaFuncAttributeMaxDynamicSharedMemorySize, smem_bytes(32, 1, 16));
    cudaFuncSetAttribute(conv5_bf16_kernel<32, 64, 32, 128, 2, 8, true, false>,
                         cudaFuncAttributeMaxDynamicSharedMemorySize, smem_bytes(32, 2, 8));
    cudaFuncSetAttribute(conv5_bf16_kernel<64, 64, 32, 128, 1, 16, true, true>,
                         cudaFuncAttributeMaxDynamicSharedMemorySize, smem_bytes(32, 1, 16));

    // generate per-batch conv kernels (bf16 hi/lo split, mma layout)
    {
        int t;
        t = 16 * 1 * 25 * 8 * 16;
        genw_bf16_kernel<<<(t + 255) / 256, 256>>>(w[0], wb[0], action, k1, 4, 1, 16);
        genw_bf16_kernel<<<(t + 255) / 256, 256>>>(w[1], wb[1], action, k2, 16, 1, 16);
        t = 16 * 1 * 25 * 8 * 32;
        genw_bf16_kernel<<<(t + 255) / 256, 256>>>(w[2], wb[2], action, k3, 16, 1, 32);
        t = 16 * 2 * 25 * 8 * 32;
        genw_bf16_kernel<<<(t + 255) / 256, 256>>>(w[3], wb[3], action, k4, 32, 2, 32);
        t = 16 * 2 * 25 * 8 * 64;
        genw_bf16_kernel<<<(t + 255) / 256, 256>>>(w[4], wb[4], action, k5, 32, 2, 64);
        t = 16 * 4 * 25 * 8 * 64;
        genw_bf16_kernel<<<(t + 255) / 256, 256>>>(w[5], wb[5], action, k6, 64, 4, 64);
    }
    genw_kernel<<<(256 * 16 + 255) / 256, 256>>>(w[6], wb[6], action, k7, 256);

    // bn0 stats on x
    stats_kernel<65536><<<16 * 4, 256>>>(x, bns[0], bnb[0], aff + 0 * AOFF, 4);
    // conv1: bn0(x) -> t1
    conv5_bf16_kernel<4, 16, 16, 256, 2, 8, true, false>
        <<<dim3(8, 32, 16), 256, smem_bytes(16, 2, 8)>>>(x, aff + 0 * AOFF, k1, t1);
    // bn1 stats
    stats_kernel<65536><<<16 * 16, 256>>>(t1, bns[1], bnb[1], aff + 1 * AOFF, 16);
    // conv2: relu(bn1(t1)) -> t2
    conv5_bf16_kernel<16, 16, 16, 256, 1, 16, true, true>
        <<<dim3(8, 16, 16), 256, smem_bytes(16, 1, 16)>>>(t1, aff + 1 * AOFF, k2, t2);
    // bn2 stats
    stats_kernel<65536><<<16 * 16, 256>>>(t2, bns[2], bnb[2], aff + 2 * AOFF, 16);
    // avgpool(bn2(t2)) -> t3 (normalized)
    avgpool_kernel<<<(16 * 16 * 128 * 128 + 255) / 256, 256>>>(t2, aff + 2 * AOFF, t3);
    // conv3: t3 -> t4
    conv5_bf16_kernel<16, 32, 32, 128, 2, 8, false, false>
        <<<dim3(4, 16, 16), 256, smem_bytes(32, 2, 8)>>>(t3, aff, k3, t4);
    // bn3 stats
    stats_kernel<16384><<<16 * 32, 256>>>(t4, bns[3], bnb[3], aff + 3 * AOFF, 32);
    // conv4: relu(bn3(t4)) -> t5
    conv5_bf16_kernel<32, 32, 32, 128, 1, 16, true, true>
        <<<dim3(4, 8, 16), 256, smem_bytes(32, 1, 16)>>>(t4, aff + 3 * AOFF, k4, t5);
    // bn4 stats
    stats_kernel<16384><<<16 * 32, 256>>>(t5, bns[4], bnb[4], aff + 4 * AOFF, 32);
    // conv5: bn4(t5) -> t6
    conv5_bf16_kernel<32, 64, 32, 128, 2, 8, true, false>
        <<<dim3(4, 32, 16), 256, smem_bytes(32, 2, 8)>>>(t5, aff + 4 * AOFF, k5, t6);
    // bn5 stats
    stats_kernel<16384><<<16 * 64, 256>>>(t6, bns[5], bnb[5], aff + 5 * AOFF, 64);
    // conv6: relu(bn5(t6)) -> t7
    conv5_bf16_kernel<64, 64, 32, 128, 1, 16, true, true>
        <<<dim3(4, 16, 16), 256, smem_bytes(32, 1, 16)>>>(t6, aff + 5 * AOFF, k6, t7);
    // bn6 stats
    stats_kernel<16384><<<16 * 64, 256>>>(t7, bns[6], bnb[6], aff + 6 * AOFF, 64);
    // conv7 1x1: bn6(t7) -> t8
    conv1x1_kernel<<<dim3(64, 16), 256>>>(t7, aff + 6 * AOFF, k7, t8);
    // upsample + residual
    up_add_kernel<<<(16 * 4 * 256 * 256 + 255) / 256, 256>>>(t8, x, (float*)d_out);
}